// round 2
// baseline (speedup 1.0000x reference)
#include <cuda_runtime.h>

// ---------------------------------------------------------------------------
// Problem constants
// ---------------------------------------------------------------------------
#define BATCH 16
#define SEQ_S 1024
#define SEQ_T 2048
#define DIM   512
#define CF    2560   // C * Fdim = 128 * 20
#define MELD  1280   // 20 * 64

// GEMM tiling
#define BM 64
#define BN 64
#define BK 16

// ---------------------------------------------------------------------------
// Scratch (static device globals -- no allocation allowed)
// ---------------------------------------------------------------------------
__device__ float g_k  [BATCH * SEQ_S * DIM];          //  33.5 MB
__device__ float g_v  [BATCH * SEQ_S * DIM];          //  33.5 MB
__device__ float g_q  [BATCH * SEQ_T * DIM];          //  67 MB
__device__ float g_att[BATCH * SEQ_T * SEQ_S];        // 134 MB
__device__ float g_val[BATCH * SEQ_T * DIM];          //  67 MB

// ---------------------------------------------------------------------------
// lengths may be int64 or int32 (jax x64 flag dependent). Detect on device:
// values are in [1, 1024]; an int64 view of element 0 over int32 storage is
// >= 2^32 because lengths[1] >= 1.
// ---------------------------------------------------------------------------
__device__ __forceinline__ int get_len(const void* lp, int b) {
    const long long* l8 = (const long long*)lp;
    long long v0 = l8[0];
    if (v0 >= 1 && v0 <= 0x7fffffffLL) {
        return (int)l8[b];
    }
    return ((const int*)lp)[b];
}

// ---------------------------------------------------------------------------
// Kernel 1: k = ph @ Wk + bk  and  v = ph @ Wv + bv   (blockIdx.z selects)
// ph flat: [B*S, 512]
// ---------------------------------------------------------------------------
__global__ void kv_kernel(const float* __restrict__ ph,
                          const float* __restrict__ Wk, const float* __restrict__ bk,
                          const float* __restrict__ Wv, const float* __restrict__ bv) {
    const float* Bm   = blockIdx.z ? Wv : Wk;
    const float* bias = blockIdx.z ? bv : bk;
    float*       C    = blockIdx.z ? g_v : g_k;
    const int K = DIM, N = DIM;

    __shared__ float As[BK][BM];
    __shared__ float Bs[BK][BN];

    int tid = threadIdx.x;
    int bm = blockIdx.y * BM, bn = blockIdx.x * BN;
    int ar = tid >> 2, ac = (tid & 3) * 4;
    int br = tid >> 4, bc = (tid & 15) * 4;
    int tm = (tid >> 4) * 4, tn = (tid & 15) * 4;
    float acc[4][4] = {};

    for (int k0 = 0; k0 < K; k0 += BK) {
        float4 a4 = *(const float4*)(ph + (size_t)(bm + ar) * K + k0 + ac);
        As[ac + 0][ar] = a4.x; As[ac + 1][ar] = a4.y;
        As[ac + 2][ar] = a4.z; As[ac + 3][ar] = a4.w;
        *(float4*)&Bs[br][bc] = *(const float4*)(Bm + (size_t)(k0 + br) * N + bn + bc);
        __syncthreads();
        #pragma unroll
        for (int k = 0; k < BK; k++) {
            float a[4], b[4];
            #pragma unroll
            for (int i = 0; i < 4; i++) a[i] = As[k][tm + i];
            #pragma unroll
            for (int j = 0; j < 4; j++) b[j] = Bs[k][tn + j];
            #pragma unroll
            for (int i = 0; i < 4; i++)
                #pragma unroll
                for (int j = 0; j < 4; j++) acc[i][j] += a[i] * b[j];
        }
        __syncthreads();
    }
    float4 bb = *(const float4*)(bias + bn + tn);
    #pragma unroll
    for (int i = 0; i < 4; i++) {
        float4 o = make_float4(acc[i][0] + bb.x, acc[i][1] + bb.y,
                               acc[i][2] + bb.z, acc[i][3] + bb.w);
        *(float4*)(C + (size_t)(bm + tm + i) * N + bn + tn) = o;
    }
}

// ---------------------------------------------------------------------------
// Kernel 2: q[b,t,:] = sum_cf g[b,cf,t] * Wq[cf,:] + bq
// g: [B, 2560, 2048] -> A read transposed; coalesced along t.
// ---------------------------------------------------------------------------
__global__ void q_kernel(const float* __restrict__ g,
                         const float* __restrict__ Wq, const float* __restrict__ bq) {
    const int K = CF, N = DIM;
    int z = blockIdx.z;
    const float* gb = g + (size_t)z * CF * SEQ_T;
    float*       C  = g_q + (size_t)z * SEQ_T * DIM;

    __shared__ float As[BK][BM];
    __shared__ float Bs[BK][BN];

    int tid = threadIdx.x;
    int bm = blockIdx.y * BM, bn = blockIdx.x * BN;
    int cfl = tid >> 4, tl = (tid & 15) * 4;      // A-tile: 16 cf rows x 64 t cols
    int br = tid >> 4, bc = (tid & 15) * 4;
    int tm = (tid >> 4) * 4, tn = (tid & 15) * 4;
    float acc[4][4] = {};

    for (int k0 = 0; k0 < K; k0 += BK) {
        // coalesced along t; store directly in As[k][m] layout
        *(float4*)&As[cfl][tl] =
            *(const float4*)(gb + (size_t)(k0 + cfl) * SEQ_T + bm + tl);
        *(float4*)&Bs[br][bc] = *(const float4*)(Wq + (size_t)(k0 + br) * N + bn + bc);
        __syncthreads();
        #pragma unroll
        for (int k = 0; k < BK; k++) {
            float a[4], b[4];
            #pragma unroll
            for (int i = 0; i < 4; i++) a[i] = As[k][tm + i];
            #pragma unroll
            for (int j = 0; j < 4; j++) b[j] = Bs[k][tn + j];
            #pragma unroll
            for (int i = 0; i < 4; i++)
                #pragma unroll
                for (int j = 0; j < 4; j++) acc[i][j] += a[i] * b[j];
        }
        __syncthreads();
    }
    float4 bb = *(const float4*)(bq + bn + tn);
    #pragma unroll
    for (int i = 0; i < 4; i++) {
        float4 o = make_float4(acc[i][0] + bb.x, acc[i][1] + bb.y,
                               acc[i][2] + bb.z, acc[i][3] + bb.w);
        *(float4*)(C + (size_t)(bm + tm + i) * N + bn + tn) = o;
    }
}

// ---------------------------------------------------------------------------
// Kernel 3: att[b,t,s] = dot(q[b,t,:], k[b,s,:]) / sqrt(512)   (NT gemm)
// ---------------------------------------------------------------------------
__global__ void scores_kernel() {
    const int K = DIM, N = SEQ_S;
    const float scale = 0.04419417382415922f;  // 1/sqrt(512)
    int z = blockIdx.z;
    const float* A  = g_q + (size_t)z * SEQ_T * DIM;
    const float* kb = g_k + (size_t)z * SEQ_S * DIM;
    float*       C  = g_att + (size_t)z * SEQ_T * SEQ_S;

    __shared__ float As[BK][BM];
    __shared__ float Bs[BK][BN];

    int tid = threadIdx.x;
    int bm = blockIdx.y * BM, bn = blockIdx.x * BN;
    int ar = tid >> 2, ac = (tid & 3) * 4;
    int sl = tid >> 2, dl = (tid & 3) * 4;       // B-tile: 64 s rows x 16 d cols
    int tm = (tid >> 4) * 4, tn = (tid & 15) * 4;
    float acc[4][4] = {};

    for (int k0 = 0; k0 < K; k0 += BK) {
        float4 a4 = *(const float4*)(A + (size_t)(bm + ar) * K + k0 + ac);
        As[ac + 0][ar] = a4.x; As[ac + 1][ar] = a4.y;
        As[ac + 2][ar] = a4.z; As[ac + 3][ar] = a4.w;
        float4 b4 = *(const float4*)(kb + (size_t)(bn + sl) * DIM + k0 + dl);
        Bs[dl + 0][sl] = b4.x; Bs[dl + 1][sl] = b4.y;
        Bs[dl + 2][sl] = b4.z; Bs[dl + 3][sl] = b4.w;
        __syncthreads();
        #pragma unroll
        for (int k = 0; k < BK; k++) {
            float a[4], b[4];
            #pragma unroll
            for (int i = 0; i < 4; i++) a[i] = As[k][tm + i];
            #pragma unroll
            for (int j = 0; j < 4; j++) b[j] = Bs[k][tn + j];
            #pragma unroll
            for (int i = 0; i < 4; i++)
                #pragma unroll
                for (int j = 0; j < 4; j++) acc[i][j] += a[i] * b[j];
        }
        __syncthreads();
    }
    #pragma unroll
    for (int i = 0; i < 4; i++) {
        float4 o = make_float4(acc[i][0] * scale, acc[i][1] * scale,
                               acc[i][2] * scale, acc[i][3] * scale);
        *(float4*)(C + (size_t)(bm + tm + i) * N + bn + tn) = o;
    }
}

// ---------------------------------------------------------------------------
// Kernel 4: masked softmax over s (row length 1024). One block per (b,t) row.
// Masked positions (s >= len[b]) get weight 0.
// ---------------------------------------------------------------------------
__global__ void softmax_kernel(const void* __restrict__ lengths) {
    int row = blockIdx.x;                // b*2048 + t
    int b = row >> 11;
    float* p = g_att + (size_t)row * SEQ_S;
    int len = get_len(lengths, b);
    int tid = threadIdx.x;

    float4 x = ((const float4*)p)[tid];
    int s0 = tid * 4;

    __shared__ float red_m[8];
    __shared__ float red_s[8];

    float m = -1e30f;
    if (s0 + 0 < len) m = fmaxf(m, x.x);
    if (s0 + 1 < len) m = fmaxf(m, x.y);
    if (s0 + 2 < len) m = fmaxf(m, x.z);
    if (s0 + 3 < len) m = fmaxf(m, x.w);
    #pragma unroll
    for (int o = 16; o > 0; o >>= 1) m = fmaxf(m, __shfl_xor_sync(0xffffffffu, m, o));
    if ((tid & 31) == 0) red_m[tid >> 5] = m;
    __syncthreads();
    if (tid < 32) {
        float mm = (tid < 8) ? red_m[tid] : -1e30f;
        #pragma unroll
        for (int o = 4; o > 0; o >>= 1) mm = fmaxf(mm, __shfl_xor_sync(0xffffffffu, mm, o));
        if (tid == 0) red_m[0] = mm;
    }
    __syncthreads();
    m = red_m[0];

    float e0 = (s0 + 0 < len) ? __expf(x.x - m) : 0.f;
    float e1 = (s0 + 1 < len) ? __expf(x.y - m) : 0.f;
    float e2 = (s0 + 2 < len) ? __expf(x.z - m) : 0.f;
    float e3 = (s0 + 3 < len) ? __expf(x.w - m) : 0.f;
    float s = e0 + e1 + e2 + e3;
    #pragma unroll
    for (int o = 16; o > 0; o >>= 1) s += __shfl_xor_sync(0xffffffffu, s, o);
    if ((tid & 31) == 0) red_s[tid >> 5] = s;
    __syncthreads();
    if (tid < 32) {
        float ss = (tid < 8) ? red_s[tid] : 0.f;
        #pragma unroll
        for (int o = 4; o > 0; o >>= 1) ss += __shfl_xor_sync(0xffffffffu, ss, o);
        if (tid == 0) red_s[0] = ss;
    }
    __syncthreads();
    float inv = 1.0f / red_s[0];

    ((float4*)p)[tid] = make_float4(e0 * inv, e1 * inv, e2 * inv, e3 * inv);
}

// ---------------------------------------------------------------------------
// Kernel 5: value = att @ v   (NN gemm per batch, K=1024)
// ---------------------------------------------------------------------------
__global__ void value_kernel() {
    const int K = SEQ_S, N = DIM;
    int z = blockIdx.z;
    const float* A  = g_att + (size_t)z * SEQ_T * SEQ_S;
    const float* Bm = g_v   + (size_t)z * SEQ_S * DIM;
    float*       C  = g_val + (size_t)z * SEQ_T * DIM;

    __shared__ float As[BK][BM];
    __shared__ float Bs[BK][BN];

    int tid = threadIdx.x;
    int bm = blockIdx.y * BM, bn = blockIdx.x * BN;
    int ar = tid >> 2, ac = (tid & 3) * 4;
    int br = tid >> 4, bc = (tid & 15) * 4;
    int tm = (tid >> 4) * 4, tn = (tid & 15) * 4;
    float acc[4][4] = {};

    for (int k0 = 0; k0 < K; k0 += BK) {
        float4 a4 = *(const float4*)(A + (size_t)(bm + ar) * K + k0 + ac);
        As[ac + 0][ar] = a4.x; As[ac + 1][ar] = a4.y;
        As[ac + 2][ar] = a4.z; As[ac + 3][ar] = a4.w;
        *(float4*)&Bs[br][bc] = *(const float4*)(Bm + (size_t)(k0 + br) * N + bn + bc);
        __syncthreads();
        #pragma unroll
        for (int k = 0; k < BK; k++) {
            float a[4], b[4];
            #pragma unroll
            for (int i = 0; i < 4; i++) a[i] = As[k][tm + i];
            #pragma unroll
            for (int j = 0; j < 4; j++) b[j] = Bs[k][tn + j];
            #pragma unroll
            for (int i = 0; i < 4; i++)
                #pragma unroll
                for (int j = 0; j < 4; j++) acc[i][j] += a[i] * b[j];
        }
        __syncthreads();
    }
    #pragma unroll
    for (int i = 0; i < 4; i++) {
        float4 o = make_float4(acc[i][0], acc[i][1], acc[i][2], acc[i][3]);
        *(float4*)(C + (size_t)(bm + tm + i) * N + bn + tn) = o;
    }
}

// ---------------------------------------------------------------------------
// Kernel 6: out = value @ Wmel + bmel, stored transposed:
// col n -> (f = n/64, j = n%64); out[b, j, f, t]. t contiguous -> float4 along t.
// ---------------------------------------------------------------------------
__global__ void out_kernel(const float* __restrict__ Wmel,
                           const float* __restrict__ bmel,
                           float* __restrict__ out) {
    const int K = DIM, N = MELD;
    int z = blockIdx.z;
    const float* A = g_val + (size_t)z * SEQ_T * DIM;

    __shared__ float As[BK][BM];
    __shared__ float Bs[BK][BN];

    int tid = threadIdx.x;
    int bm = blockIdx.y * BM, bn = blockIdx.x * BN;
    int ar = tid >> 2, ac = (tid & 3) * 4;
    int br = tid >> 4, bc = (tid & 15) * 4;
    int tm = (tid >> 4) * 4, tn = (tid & 15) * 4;
    float acc[4][4] = {};

    for (int k0 = 0; k0 < K; k0 += BK) {
        float4 a4 = *(const float4*)(A + (size_t)(bm + ar) * K + k0 + ac);
        As[ac + 0][ar] = a4.x; As[ac + 1][ar] = a4.y;
        As[ac + 2][ar] = a4.z; As[ac + 3][ar] = a4.w;
        *(float4*)&Bs[br][bc] = *(const float4*)(Wmel + (size_t)(k0 + br) * N + bn + bc);
        __syncthreads();
        #pragma unroll
        for (int k = 0; k < BK; k++) {
            float a[4], b[4];
            #pragma unroll
            for (int i = 0; i < 4; i++) a[i] = As[k][tm + i];
            #pragma unroll
            for (int j = 0; j < 4; j++) b[j] = Bs[k][tn + j];
            #pragma unroll
            for (int i = 0; i < 4; i++)
                #pragma unroll
                for (int j = 0; j < 4; j++) acc[i][j] += a[i] * b[j];
        }
        __syncthreads();
    }
    int t0 = bm + tm;
    #pragma unroll
    for (int j = 0; j < 4; j++) {
        int n = bn + tn + j;
        float bv_ = bmel[n];
        float4 o = make_float4(acc[0][j] + bv_, acc[1][j] + bv_,
                               acc[2][j] + bv_, acc[3][j] + bv_);
        size_t idx = ((size_t)z * (64 * 20) + (size_t)(n & 63) * 20 + (n >> 6))
                     * (size_t)SEQ_T + t0;
        *(float4*)(out + idx) = o;
    }
}

// ---------------------------------------------------------------------------
// Launch
// ---------------------------------------------------------------------------
extern "C" void kernel_launch(void* const* d_in, const int* in_sizes, int n_in,
                              void* d_out, int out_size) {
    const float* ph   = (const float*)d_in[0];
    const float* g    = (const float*)d_in[1];
    const void*  lens = d_in[2];
    const float* Wk   = (const float*)d_in[3];
    const float* bk   = (const float*)d_in[4];
    const float* Wv   = (const float*)d_in[5];
    const float* bv   = (const float*)d_in[6];
    const float* Wq   = (const float*)d_in[7];
    const float* bq   = (const float*)d_in[8];
    const float* Wmel = (const float*)d_in[9];
    const float* bmel = (const float*)d_in[10];
    float* out = (float*)d_out;

    dim3 blk(256);
    kv_kernel   <<<dim3(DIM / BN, (BATCH * SEQ_S) / BM, 2), blk>>>(ph, Wk, bk, Wv, bv);
    q_kernel    <<<dim3(DIM / BN,  SEQ_T / BM, BATCH), blk>>>(g, Wq, bq);
    scores_kernel<<<dim3(SEQ_S / BN, SEQ_T / BM, BATCH), blk>>>();
    softmax_kernel<<<BATCH * SEQ_T, 256>>>(lens);
    value_kernel<<<dim3(DIM / BN,  SEQ_T / BM, BATCH), blk>>>();
    out_kernel  <<<dim3(MELD / BN, SEQ_T / BM, BATCH), blk>>>(Wmel, bmel, out);
}

// round 4
// speedup vs baseline: 2.7923x; 2.7923x over previous
#include <cuda_runtime.h>
#include <cstdint>

// ---------------------------------------------------------------------------
// Problem constants
// ---------------------------------------------------------------------------
#define BATCH 16
#define SEQ_S 1024
#define SEQ_T 2048
#define DIM   512
#define CF    2560   // C * Fdim
#define MELD  1280

// GEMM tiling (tf32 mma.sync)
#define TBM 128
#define TBN 128
#define TBK 16
#define SAS 136      // smem stride for A tile rows (BM + 8): conflict-free frag loads
#define SBS 136      // smem stride for B tile rows (BN + 8)
#define SMEM_FLOATS (TBK * SAS + TBK * SBS)   // 4352 floats = 17408 B

// ---------------------------------------------------------------------------
// Scratch
// ---------------------------------------------------------------------------
__device__ float g_k  [BATCH * SEQ_S * DIM];
__device__ float g_v  [BATCH * SEQ_S * DIM];
__device__ float g_q  [BATCH * SEQ_T * DIM];
__device__ float g_att[BATCH * SEQ_T * SEQ_S];
__device__ float g_val[BATCH * SEQ_T * DIM];

// ---------------------------------------------------------------------------
__device__ __forceinline__ int get_len(const void* lp, int b) {
    const long long* l8 = (const long long*)lp;
    long long v0 = l8[0];
    if (v0 >= 1 && v0 <= 0x7fffffffLL) return (int)l8[b];
    return ((const int*)lp)[b];
}

__device__ __forceinline__ float ftf32(float x) {
    uint32_t u;
    asm("cvt.rna.tf32.f32 %0, %1;" : "=r"(u) : "f"(x));
    return __uint_as_float(u);
}
__device__ __forceinline__ float4 ftf32_4(float4 v) {
    return make_float4(ftf32(v.x), ftf32(v.y), ftf32(v.z), ftf32(v.w));
}

#define MMA_TF32(d, a, b)                                                     \
    asm volatile(                                                             \
        "mma.sync.aligned.m16n8k8.row.col.f32.tf32.tf32.f32 "                 \
        "{%0,%1,%2,%3}, {%4,%5,%6,%7}, {%8,%9}, {%0,%1,%2,%3};\n"             \
        : "+f"(d.x), "+f"(d.y), "+f"(d.z), "+f"(d.w)                          \
        : "r"(a[0]), "r"(a[1]), "r"(a[2]), "r"(a[3]), "r"(b[0]), "r"(b[1]))

// ---------------------------------------------------------------------------
// Unified tf32 GEMM.
//   A_COL: 0 -> A row-major [M,K] (lda=K stride between rows)
//          1 -> A stored [K,M]   (lda=M stride between k-rows; the g tensor)
//   B_TR : 0 -> B row-major [K,N]
//          1 -> B stored [N,K] (NT gemm; the k matrix for scores)
//   EPI  : 0 = +bias, 1 = *scale, 2 = none, 3 = mel transposed store (+bias)
// ---------------------------------------------------------------------------
template<int A_COL, int B_TR, int EPI>
__global__ __launch_bounds__(256, 2)
void gemm_tf32(const float* __restrict__ Aall, int lda, long long strideA,
               const float* __restrict__ Ball, int ldb, long long strideB,
               const float* __restrict__ bias,
               float* __restrict__ Call, int ldc, long long strideC,
               int Kdim, float scale) {
    __shared__ __align__(16) float smem[SMEM_FLOATS];
    float* As = smem;
    float* Bs = smem + TBK * SAS;

    const int z = blockIdx.z;
    const float* A = Aall + (size_t)z * strideA;
    const float* Bp = Ball + (size_t)z * strideB;
    float* C = Call + (size_t)z * strideC;

    const int bm = blockIdx.y * TBM;
    const int bn = blockIdx.x * TBN;

    const int tid = threadIdx.x;
    const int warp = tid >> 5, lane = tid & 31;
    const int wm = warp & 1, wn = warp >> 1;   // 2 x 4 warp grid
    const int g = lane >> 2, tg = lane & 3;

    float4 acc[4][4];
    #pragma unroll
    for (int i = 0; i < 4; i++)
        #pragma unroll
        for (int j = 0; j < 4; j++) acc[i][j] = make_float4(0.f, 0.f, 0.f, 0.f);

    for (int k0 = 0; k0 < Kdim; k0 += TBK) {
        // ---- load A tile into As[k][m] ----
        if (A_COL == 0) {
            int r = tid >> 2, c4 = (tid & 3) << 2;
            #pragma unroll
            for (int p = 0; p < 2; p++) {
                int row = r + p * 64;
                float4 v = *(const float4*)(A + (size_t)(bm + row) * lda + k0 + c4);
                As[(c4 + 0) * SAS + row] = ftf32(v.x);
                As[(c4 + 1) * SAS + row] = ftf32(v.y);
                As[(c4 + 2) * SAS + row] = ftf32(v.z);
                As[(c4 + 3) * SAS + row] = ftf32(v.w);
            }
        } else {
            int kr = tid >> 4, m4 = (tid & 15) << 2;
            #pragma unroll
            for (int p = 0; p < 2; p++) {
                int m = m4 + p * 64;
                float4 v = *(const float4*)(A + (size_t)(k0 + kr) * lda + bm + m);
                *(float4*)(As + kr * SAS + m) = ftf32_4(v);
            }
        }
        // ---- load B tile into Bs[k][n] ----
        if (B_TR == 0) {
            int kr = tid >> 5, n4 = (tid & 31) << 2;
            #pragma unroll
            for (int p = 0; p < 2; p++) {
                int k = kr + p * 8;
                float4 v = *(const float4*)(Bp + (size_t)(k0 + k) * ldb + bn + n4);
                *(float4*)(Bs + k * SBS + n4) = ftf32_4(v);
            }
        } else {
            int r = tid >> 2, c4 = (tid & 3) << 2;
            #pragma unroll
            for (int p = 0; p < 2; p++) {
                int n = r + p * 64;
                float4 v = *(const float4*)(Bp + (size_t)(bn + n) * ldb + k0 + c4);
                Bs[(c4 + 0) * SBS + n] = ftf32(v.x);
                Bs[(c4 + 1) * SBS + n] = ftf32(v.y);
                Bs[(c4 + 2) * SBS + n] = ftf32(v.z);
                Bs[(c4 + 3) * SBS + n] = ftf32(v.w);
            }
        }
        __syncthreads();

        #pragma unroll
        for (int kk = 0; kk < TBK; kk += 8) {
            uint32_t af[4][4], bf[4][2];
            #pragma unroll
            for (int mi = 0; mi < 4; mi++) {
                int m0 = wm * 64 + mi * 16;
                af[mi][0] = __float_as_uint(As[(kk + tg) * SAS + m0 + g]);
                af[mi][1] = __float_as_uint(As[(kk + tg) * SAS + m0 + g + 8]);
                af[mi][2] = __float_as_uint(As[(kk + tg + 4) * SAS + m0 + g]);
                af[mi][3] = __float_as_uint(As[(kk + tg + 4) * SAS + m0 + g + 8]);
            }
            #pragma unroll
            for (int ni = 0; ni < 4; ni++) {
                int n0 = wn * 32 + ni * 8;
                bf[ni][0] = __float_as_uint(Bs[(kk + tg) * SBS + n0 + g]);
                bf[ni][1] = __float_as_uint(Bs[(kk + tg + 4) * SBS + n0 + g]);
            }
            #pragma unroll
            for (int mi = 0; mi < 4; mi++)
                #pragma unroll
                for (int ni = 0; ni < 4; ni++)
                    MMA_TF32(acc[mi][ni], af[mi], bf[ni]);
        }
        __syncthreads();
    }

    // ---- epilogue ----
    if (EPI != 3) {
        #pragma unroll
        for (int mi = 0; mi < 4; mi++) {
            #pragma unroll
            for (int ni = 0; ni < 4; ni++) {
                int row = bm + wm * 64 + mi * 16 + g;
                int col = bn + wn * 32 + ni * 8 + 2 * tg;
                float4 a = acc[mi][ni];
                if (EPI == 0) {
                    float b0 = bias[col], b1 = bias[col + 1];
                    a.x += b0; a.y += b1; a.z += b0; a.w += b1;
                } else if (EPI == 1) {
                    a.x *= scale; a.y *= scale; a.z *= scale; a.w *= scale;
                }
                C[(size_t)row * ldc + col]       = a.x;
                C[(size_t)row * ldc + col + 1]   = a.y;
                C[(size_t)(row + 8) * ldc + col]     = a.z;
                C[(size_t)(row + 8) * ldc + col + 1] = a.w;
            }
        }
    } else {
        // mel: out[b, n%64, n/64, t], t contiguous. Stage 32-col chunks via smem.
        float* sc = smem;  // [32][132] = 4224 floats, reuses As/Bs
        #pragma unroll 1
        for (int p = 0; p < 4; p++) {
            __syncthreads();
            if (wn == p) {
                #pragma unroll
                for (int mi = 0; mi < 4; mi++) {
                    #pragma unroll
                    for (int ni = 0; ni < 4; ni++) {
                        int ml = wm * 64 + mi * 16 + g;
                        int nl = ni * 8 + 2 * tg;
                        int ncol = bn + p * 32 + nl;
                        float b0 = bias[ncol], b1 = bias[ncol + 1];
                        float4 a = acc[mi][ni];
                        sc[nl * 132 + ml]           = a.x + b0;
                        sc[(nl + 1) * 132 + ml]     = a.y + b1;
                        sc[nl * 132 + ml + 8]       = a.z + b0;
                        sc[(nl + 1) * 132 + ml + 8] = a.w + b1;
                    }
                }
            }
            __syncthreads();
            int nl = tid >> 3, mq = (tid & 7) << 2;
            int ncol = bn + p * 32 + nl;
            size_t obase = ((size_t)z * 1280 + (size_t)(ncol & 63) * 20 + (ncol >> 6))
                           * (size_t)SEQ_T;
            #pragma unroll
            for (int it = 0; it < 4; it++) {
                int m = mq + it * 32;
                float4 v = *(float4*)(sc + nl * 132 + m);
                *(float4*)(Call + obase + bm + m) = v;
            }
        }
    }
}

// ---------------------------------------------------------------------------
// masked softmax over s (row length 1024)
// ---------------------------------------------------------------------------
__global__ void softmax_kernel(const void* __restrict__ lengths) {
    int row = blockIdx.x;
    int b = row >> 11;
    float* p = g_att + (size_t)row * SEQ_S;
    int len = get_len(lengths, b);
    int tid = threadIdx.x;

    float4 x = ((const float4*)p)[tid];
    int s0 = tid * 4;

    __shared__ float red_m[8];
    __shared__ float red_s[8];

    float m = -1e30f;
    if (s0 + 0 < len) m = fmaxf(m, x.x);
    if (s0 + 1 < len) m = fmaxf(m, x.y);
    if (s0 + 2 < len) m = fmaxf(m, x.z);
    if (s0 + 3 < len) m = fmaxf(m, x.w);
    #pragma unroll
    for (int o = 16; o > 0; o >>= 1) m = fmaxf(m, __shfl_xor_sync(0xffffffffu, m, o));
    if ((tid & 31) == 0) red_m[tid >> 5] = m;
    __syncthreads();
    if (tid < 32) {
        float mm = (tid < 8) ? red_m[tid] : -1e30f;
        #pragma unroll
        for (int o = 4; o > 0; o >>= 1) mm = fmaxf(mm, __shfl_xor_sync(0xffffffffu, mm, o));
        if (tid == 0) red_m[0] = mm;
    }
    __syncthreads();
    m = red_m[0];

    float e0 = (s0 + 0 < len) ? __expf(x.x - m) : 0.f;
    float e1 = (s0 + 1 < len) ? __expf(x.y - m) : 0.f;
    float e2 = (s0 + 2 < len) ? __expf(x.z - m) : 0.f;
    float e3 = (s0 + 3 < len) ? __expf(x.w - m) : 0.f;
    float s = e0 + e1 + e2 + e3;
    #pragma unroll
    for (int o = 16; o > 0; o >>= 1) s += __shfl_xor_sync(0xffffffffu, s, o);
    if ((tid & 31) == 0) red_s[tid >> 5] = s;
    __syncthreads();
    if (tid < 32) {
        float ss = (tid < 8) ? red_s[tid] : 0.f;
        #pragma unroll
        for (int o = 4; o > 0; o >>= 1) ss += __shfl_xor_sync(0xffffffffu, ss, o);
        if (tid == 0) red_s[0] = ss;
    }
    __syncthreads();
    float inv = 1.0f / red_s[0];

    ((float4*)p)[tid] = make_float4(e0 * inv, e1 * inv, e2 * inv, e3 * inv);
}

// ---------------------------------------------------------------------------
extern "C" void kernel_launch(void* const* d_in, const int* in_sizes, int n_in,
                              void* d_out, int out_size) {
    const float* ph   = (const float*)d_in[0];
    const float* g    = (const float*)d_in[1];
    const void*  lens = d_in[2];
    const float* Wk   = (const float*)d_in[3];
    const float* bk   = (const float*)d_in[4];
    const float* Wv   = (const float*)d_in[5];
    const float* bv   = (const float*)d_in[6];
    const float* Wq   = (const float*)d_in[7];
    const float* bq   = (const float*)d_in[8];
    const float* Wmel = (const float*)d_in[9];
    const float* bmel = (const float*)d_in[10];
    float* out = (float*)d_out;

    float* dk;  cudaGetSymbolAddress((void**)&dk,  g_k);
    float* dv;  cudaGetSymbolAddress((void**)&dv,  g_v);
    float* dq;  cudaGetSymbolAddress((void**)&dq,  g_q);
    float* datt; cudaGetSymbolAddress((void**)&datt, g_att);
    float* dval; cudaGetSymbolAddress((void**)&dval, g_val);

    const float scale = 0.04419417382415922f;  // 1/sqrt(512)
    dim3 blk(256);

    // k = ph @ Wk + bk ; v = ph @ Wv + bv   (M=16384, K=512, N=512)
    gemm_tf32<0,0,0><<<dim3(4, 128, 1), blk>>>(ph, DIM, 0, Wk, DIM, 0, bk,
                                               dk, DIM, 0, DIM, 1.f);
    gemm_tf32<0,0,0><<<dim3(4, 128, 1), blk>>>(ph, DIM, 0, Wv, DIM, 0, bv,
                                               dv, DIM, 0, DIM, 1.f);
    // q = g^T @ Wq + bq   (per batch: M=2048, K=2560, N=512; A stored [K,M])
    gemm_tf32<1,0,0><<<dim3(4, 16, BATCH), blk>>>(g, SEQ_T, (long long)CF * SEQ_T,
                                                  Wq, DIM, 0, bq,
                                                  dq, DIM, (long long)SEQ_T * DIM,
                                                  CF, 1.f);
    // att = (q @ k^T) * scale   (M=2048, N=1024, K=512; B stored [N,K])
    gemm_tf32<0,1,1><<<dim3(8, 16, BATCH), blk>>>(dq, DIM, (long long)SEQ_T * DIM,
                                                  dk, DIM, (long long)SEQ_S * DIM,
                                                  nullptr,
                                                  datt, SEQ_S, (long long)SEQ_T * SEQ_S,
                                                  DIM, scale);
    softmax_kernel<<<BATCH * SEQ_T, 256>>>(lens);
    // value = att @ v   (M=2048, K=1024, N=512)
    gemm_tf32<0,0,2><<<dim3(4, 16, BATCH), blk>>>(datt, SEQ_S, (long long)SEQ_T * SEQ_S,
                                                  dv, DIM, (long long)SEQ_S * DIM,
                                                  nullptr,
                                                  dval, DIM, (long long)SEQ_T * DIM,
                                                  SEQ_S, 1.f);
    // out = value @ Wmel + bmel, transposed mel store (M=2048, K=512, N=1280)
    gemm_tf32<0,0,3><<<dim3(10, 16, BATCH), blk>>>(dval, DIM, (long long)SEQ_T * DIM,
                                                   Wmel, MELD, 0, bmel,
                                                   out, 0, 0, DIM, 1.f);
}